// round 4
// baseline (speedup 1.0000x reference)
#include <cuda_runtime.h>

// Problem constants
#define BATCH 8
#define CH    128
#define NPIX  2304     // 48*48
#define RED   16

typedef unsigned long long u64;

// ---------------- scratch (device globals: allowed; no allocation) ----------
__device__ __align__(16) float g_q[(size_t)BATCH * CH * NPIX];
__device__ __align__(16) float g_k[(size_t)BATCH * CH * NPIX];
__device__ __align__(16) float g_v[(size_t)BATCH * CH * NPIX];
__device__ __align__(16) float g_att[(size_t)BATCH * NPIX * NPIX];  // energy -> attn in place
__device__ float g_mean[BATCH * CH];
__device__ float g_se[BATCH * CH];

// ---------------- f32x2 packed-math helpers ---------------------------------
__device__ __forceinline__ u64 pack_dup(float a) {
    u64 r;
    asm("mov.b64 %0, {%1, %1};" : "=l"(r) : "f"(a));
    return r;
}
__device__ __forceinline__ void unpack2(u64 v, float& lo, float& hi) {
    asm("mov.b64 {%0, %1}, %2;" : "=f"(lo), "=f"(hi) : "l"(v));
}
__device__ __forceinline__ void ffma2(u64& d, u64 a, u64 b) {
    asm("fma.rn.f32x2 %0, %1, %2, %3;" : "=l"(d) : "l"(a), "l"(b), "l"(d));
}

// =============================================================================
// Kernel 1: QKV.  out[m][b,co,n] = sum_ci W[co,ci] * x[b,ci,n] + bias[co]
// Block: (n-tile 64, batch, matrix). 256 threads. tile 128co x 64n,
// microtile 4co x 8n (4 f32x2 pairs).
// =============================================================================
__global__ __launch_bounds__(256) void qkv_kernel(
    const float* __restrict__ x,
    const float* __restrict__ Wq, const float* __restrict__ bq,
    const float* __restrict__ Wk, const float* __restrict__ bk,
    const float* __restrict__ Wv, const float* __restrict__ bv)
{
    __shared__ __align__(16) float xs[CH * 64];
    const int n0 = blockIdx.x * 64;
    const int b  = blockIdx.y;
    const int m  = blockIdx.z;
    const float* W    = (m == 0) ? Wq : ((m == 1) ? Wk : Wv);
    const float* bias = (m == 0) ? bq : ((m == 1) ? bk : bv);
    float* outp       = (m == 0) ? g_q : ((m == 1) ? g_k : g_v);

    const int t = threadIdx.x;
    for (int idx = t; idx < CH * 64; idx += 256) {
        int ci = idx >> 6, nn = idx & 63;
        xs[idx] = x[(size_t)(b * CH + ci) * NPIX + n0 + nn];
    }
    __syncthreads();

    const int co0 = (t >> 3) << 2;   // 0..124 step 4
    const int nn0 = (t & 7) << 3;    // 0..56 step 8

    u64 acc[4][4];
#pragma unroll
    for (int u = 0; u < 4; u++)
#pragma unroll
        for (int v = 0; v < 4; v++) acc[u][v] = 0ull;

#pragma unroll 1
    for (int ci0 = 0; ci0 < CH; ci0 += 4) {
        float wr[4][4];
#pragma unroll
        for (int u = 0; u < 4; u++) {
            float4 f = *(const float4*)&W[(co0 + u) * CH + ci0];
            wr[u][0] = f.x; wr[u][1] = f.y; wr[u][2] = f.z; wr[u][3] = f.w;
        }
#pragma unroll
        for (int kk = 0; kk < 4; kk++) {
            const u64* xp = (const u64*)&xs[(ci0 + kk) * 64 + nn0];
            u64 x0 = xp[0], x1 = xp[1], x2 = xp[2], x3 = xp[3];
#pragma unroll
            for (int u = 0; u < 4; u++) {
                u64 a2 = pack_dup(wr[u][kk]);
                ffma2(acc[u][0], a2, x0);
                ffma2(acc[u][1], a2, x1);
                ffma2(acc[u][2], a2, x2);
                ffma2(acc[u][3], a2, x3);
            }
        }
    }

#pragma unroll
    for (int u = 0; u < 4; u++) {
        float bs = bias[co0 + u];
        size_t base = (size_t)(b * CH + co0 + u) * NPIX + n0 + nn0;
#pragma unroll
        for (int v = 0; v < 4; v++) {
            float o0, o1;
            unpack2(acc[u][v], o0, o1);
            outp[base + 2 * v]     = o0 + bs;
            outp[base + 2 * v + 1] = o1 + bs;
        }
    }
}

// =============================================================================
// Kernel 2: energy[b,i,j] = sum_c q[b,c,i]*k[b,c,j]
// Per-batch GEMM M=N=2304, K=128. Block tile 128x128, 256 threads, 8x8 micro.
// =============================================================================
__global__ __launch_bounds__(256, 2) void energy_kernel()
{
    __shared__ __align__(16) float As[8 * 128];
    __shared__ __align__(16) float Bs[8 * 128];
    const int j0 = blockIdx.x * 128;
    const int i0 = blockIdx.y * 128;
    const int b  = blockIdx.z;
    const float* q = g_q + (size_t)b * CH * NPIX;
    const float* k = g_k + (size_t)b * CH * NPIX;

    const int t  = threadIdx.x;
    const int lc = t >> 5;          // 0..7
    const int l4 = (t & 31) << 2;   // 0..124
    const int tx = t & 15, ty = t >> 4;

    u64 acc[8][4];
#pragma unroll
    for (int u = 0; u < 8; u++)
#pragma unroll
        for (int v = 0; v < 4; v++) acc[u][v] = 0ull;

#pragma unroll 1
    for (int c0 = 0; c0 < CH; c0 += 8) {
        float4 fa = *(const float4*)&q[(size_t)(c0 + lc) * NPIX + i0 + l4];
        float4 fb = *(const float4*)&k[(size_t)(c0 + lc) * NPIX + j0 + l4];
        __syncthreads();   // previous compute done before overwrite
        *(float4*)&As[lc * 128 + l4] = fa;
        *(float4*)&Bs[lc * 128 + l4] = fb;
        __syncthreads();
#pragma unroll
        for (int cc = 0; cc < 8; cc++) {
            float4 a0 = *(const float4*)&As[cc * 128 + ty * 8];
            float4 a1 = *(const float4*)&As[cc * 128 + ty * 8 + 4];
            float ra[8];
            ra[0] = a0.x; ra[1] = a0.y; ra[2] = a0.z; ra[3] = a0.w;
            ra[4] = a1.x; ra[5] = a1.y; ra[6] = a1.z; ra[7] = a1.w;
            const u64* bp = (const u64*)&Bs[cc * 128 + tx * 8];
            u64 rb0 = bp[0], rb1 = bp[1], rb2 = bp[2], rb3 = bp[3];
#pragma unroll
            for (int u = 0; u < 8; u++) {
                u64 a2 = pack_dup(ra[u]);
                ffma2(acc[u][0], a2, rb0);
                ffma2(acc[u][1], a2, rb1);
                ffma2(acc[u][2], a2, rb2);
                ffma2(acc[u][3], a2, rb3);
            }
        }
    }

    float* E = g_att + (size_t)b * NPIX * NPIX;
#pragma unroll
    for (int u = 0; u < 8; u++) {
        u64* op = (u64*)&E[(size_t)(i0 + ty * 8 + u) * NPIX + j0 + tx * 8];
        op[0] = acc[u][0]; op[1] = acc[u][1];
        op[2] = acc[u][2]; op[3] = acc[u][3];
    }
}

// =============================================================================
// Kernel 3: row softmax, in place on g_att.  2304 = 9*256 exactly.
// =============================================================================
__global__ __launch_bounds__(256) void softmax_kernel()
{
    const size_t row = blockIdx.x;
    float* p = g_att + row * NPIX;
    const int t = threadIdx.x;

    float v[9];
#pragma unroll
    for (int k = 0; k < 9; k++) v[k] = p[t + k * 256];

    float m = v[0];
#pragma unroll
    for (int k = 1; k < 9; k++) m = fmaxf(m, v[k]);
#pragma unroll
    for (int o = 16; o > 0; o >>= 1) m = fmaxf(m, __shfl_xor_sync(0xffffffffu, m, o));

    __shared__ float red[8];
    if ((t & 31) == 0) red[t >> 5] = m;
    __syncthreads();
    m = red[0];
#pragma unroll
    for (int r = 1; r < 8; r++) m = fmaxf(m, red[r]);

    float s = 0.f;
#pragma unroll
    for (int k = 0; k < 9; k++) { v[k] = __expf(v[k] - m); s += v[k]; }
#pragma unroll
    for (int o = 16; o > 0; o >>= 1) s += __shfl_xor_sync(0xffffffffu, s, o);
    __syncthreads();   // everyone done reading red (max) before reuse
    if ((t & 31) == 0) red[t >> 5] = s;
    __syncthreads();
    s = red[0];
#pragma unroll
    for (int r = 1; r < 8; r++) s += red[r];

    float inv = 1.0f / s;
#pragma unroll
    for (int k = 0; k < 9; k++) p[t + k * 256] = v[k] * inv;
}

// =============================================================================
// Kernel 4a: global average pool over N per (b,c)
// =============================================================================
__global__ __launch_bounds__(256) void mean_kernel(const float* __restrict__ x)
{
    const int row = blockIdx.x;   // b*CH + c
    const float* p = x + (size_t)row * NPIX;
    const int t = threadIdx.x;
    float s = 0.f;
#pragma unroll
    for (int k = 0; k < 9; k++) s += p[t + k * 256];
#pragma unroll
    for (int o = 16; o > 0; o >>= 1) s += __shfl_xor_sync(0xffffffffu, s, o);
    __shared__ float red[8];
    if ((t & 31) == 0) red[t >> 5] = s;
    __syncthreads();
    if (t == 0) {
        float tot = red[0];
#pragma unroll
        for (int r = 1; r < 8; r++) tot += red[r];
        g_mean[row] = tot * (1.0f / (float)NPIX);
    }
}

// =============================================================================
// Kernel 4b: SE MLP.  hid = relu(mean @ W1^T); se = sigmoid(hid @ W2^T)
// W1: (C/RED=8, C)  W2: (C, 8). Tiny: one block.
// =============================================================================
__global__ __launch_bounds__(128) void se_kernel(
    const float* __restrict__ w1, const float* __restrict__ w2)
{
    __shared__ float hid[BATCH * (CH / RED)];   // 8*8
    const int t = threadIdx.x;
    if (t < 64) {
        int b = t >> 3, h = t & 7;
        float s = 0.f;
#pragma unroll 4
        for (int c = 0; c < CH; c++) s += g_mean[b * CH + c] * w1[h * CH + c];
        hid[t] = fmaxf(s, 0.f);
    }
    __syncthreads();
    for (int idx = t; idx < BATCH * CH; idx += 128) {
        int b = idx >> 7, c = idx & 127;
        float s = 0.f;
#pragma unroll
        for (int h = 0; h < 8; h++) s += hid[b * 8 + h] * w2[c * 8 + h];
        g_se[idx] = 1.0f / (1.0f + __expf(-s));
    }
}

// =============================================================================
// Kernel 5: out[b,c,i] = sum_j v[b,c,j]*attn[b,i,j]; fused epilogue:
//           final = gamma*out + x*se.   GEMM M=128(c) N=2304(i) K=2304(j),
//           both operands K-contiguous -> smem transpose on load (padded).
// =============================================================================
__global__ __launch_bounds__(256, 2) void out_kernel(
    const float* __restrict__ x, const float* __restrict__ gamma,
    float* __restrict__ outp)
{
    const int JC = 16, STR = 132;
    __shared__ __align__(16) float As[16 * 132];  // [jj][c]
    __shared__ __align__(16) float Bs[16 * 132];  // [jj][i]
    const int i0 = blockIdx.x * 128;
    const int b  = blockIdx.y;
    const float* V = g_v + (size_t)b * CH * NPIX;
    const float* A = g_att + (size_t)b * NPIX * NPIX;

    const int t  = threadIdx.x;
    const int lr = t >> 2;          // 0..63
    const int jq = (t & 3) << 2;    // 0,4,8,12
    const int tx = t & 15, ty = t >> 4;

    u64 acc[8][4];
#pragma unroll
    for (int u = 0; u < 8; u++)
#pragma unroll
        for (int v = 0; v < 4; v++) acc[u][v] = 0ull;

#pragma unroll 1
    for (int j0 = 0; j0 < NPIX; j0 += JC) {
        float4 f0 = *(const float4*)&V[(size_t)(lr)      * NPIX + j0 + jq];
        float4 f1 = *(const float4*)&V[(size_t)(lr + 64) * NPIX + j0 + jq];
        float4 h0 = *(const float4*)&A[(size_t)(i0 + lr)      * NPIX + j0 + jq];
        float4 h1 = *(const float4*)&A[(size_t)(i0 + lr + 64) * NPIX + j0 + jq];
        __syncthreads();
        As[(jq + 0) * STR + lr] = f0.x;  As[(jq + 1) * STR + lr] = f0.y;
        As[(jq + 2) * STR + lr] = f0.z;  As[(jq + 3) * STR + lr] = f0.w;
        As[(jq + 0) * STR + lr + 64] = f1.x;  As[(jq + 1) * STR + lr + 64] = f1.y;
        As[(jq + 2) * STR + lr + 64] = f1.z;  As[(jq + 3) * STR + lr + 64] = f1.w;
        Bs[(jq + 0) * STR + lr] = h0.x;  Bs[(jq + 1) * STR + lr] = h0.y;
        Bs[(jq + 2) * STR + lr] = h0.z;  Bs[(jq + 3) * STR + lr] = h0.w;
        Bs[(jq + 0) * STR + lr + 64] = h1.x;  Bs[(jq + 1) * STR + lr + 64] = h1.y;
        Bs[(jq + 2) * STR + lr + 64] = h1.z;  Bs[(jq + 3) * STR + lr + 64] = h1.w;
        __syncthreads();
#pragma unroll
        for (int jj = 0; jj < JC; jj++) {
            float4 a0 = *(const float4*)&As[jj * STR + ty * 8];
            float4 a1 = *(const float4*)&As[jj * STR + ty * 8 + 4];
            float ra[8];
            ra[0] = a0.x; ra[1] = a0.y; ra[2] = a0.z; ra[3] = a0.w;
            ra[4] = a1.x; ra[5] = a1.y; ra[6] = a1.z; ra[7] = a1.w;
            const u64* bp = (const u64*)&Bs[jj * STR + tx * 8];
            u64 rb0 = bp[0], rb1 = bp[1], rb2 = bp[2], rb3 = bp[3];
#pragma unroll
            for (int u = 0; u < 8; u++) {
                u64 a2 = pack_dup(ra[u]);
                ffma2(acc[u][0], a2, rb0);
                ffma2(acc[u][1], a2, rb1);
                ffma2(acc[u][2], a2, rb2);
                ffma2(acc[u][3], a2, rb3);
            }
        }
    }

    const float gam = gamma[0];
#pragma unroll
    for (int u = 0; u < 8; u++) {
        int c = ty * 8 + u;
        float ses = g_se[b * CH + c];
        size_t base = (size_t)(b * CH + c) * NPIX + i0 + tx * 8;
#pragma unroll
        for (int v = 0; v < 4; v++) {
            float o0, o1;
            unpack2(acc[u][v], o0, o1);
            size_t off = base + 2 * v;
            outp[off]     = gam * o0 + x[off]     * ses;
            outp[off + 1] = gam * o1 + x[off + 1] * ses;
        }
    }
}

// =============================================================================
extern "C" void kernel_launch(void* const* d_in, const int* in_sizes, int n_in,
                              void* d_out, int out_size)
{
    const float* x     = (const float*)d_in[0];
    const float* Wq    = (const float*)d_in[1];
    const float* bq    = (const float*)d_in[2];
    const float* Wk    = (const float*)d_in[3];
    const float* bk    = (const float*)d_in[4];
    const float* Wv    = (const float*)d_in[5];
    const float* bv    = (const float*)d_in[6];
    const float* w1    = (const float*)d_in[7];
    const float* w2    = (const float*)d_in[8];
    const float* gamma = (const float*)d_in[9];
    float* out = (float*)d_out;

    qkv_kernel<<<dim3(NPIX / 64, BATCH, 3), 256>>>(x, Wq, bq, Wk, bk, Wv, bv);
    energy_kernel<<<dim3(NPIX / 128, NPIX / 128, BATCH), 256>>>();
    softmax_kernel<<<BATCH * NPIX, 256>>>();
    mean_kernel<<<BATCH * CH, 256>>>(x);
    se_kernel<<<1, 128>>>(w1, w2);
    out_kernel<<<dim3(NPIX / 128, BATCH), 256>>>(x, gamma, out);
}

// round 8
// speedup vs baseline: 1.7493x; 1.7493x over previous
#include <cuda_runtime.h>
#include <cuda_bf16.h>

// Problem constants
#define BATCH 8
#define CH    128
#define NPIX  2304     // 48*48
#define RED   16
#define NJT   18       // NPIX/128

typedef unsigned long long u64;
typedef unsigned u32;

// ---------------- scratch (device globals; no allocation) --------------------
__device__ __align__(16) float g_qT[(size_t)BATCH * NPIX * CH];  // [b][n][c]
__device__ __align__(16) float g_kT[(size_t)BATCH * NPIX * CH];  // [b][n][c]
__device__ __align__(16) float g_v [(size_t)BATCH * CH * NPIX];  // [b][c][n]
__device__ __align__(16) float g_att[(size_t)BATCH * NPIX * NPIX]; // exp(energy)
__device__ float g_psum[(size_t)BATCH * NPIX * NJT];
__device__ float g_rowsum[BATCH * NPIX];
__device__ float g_mean[BATCH * CH];
__device__ float g_se[BATCH * CH];

// ---------------- f32x2 packed-math helpers (qkv) ----------------------------
__device__ __forceinline__ u64 pack_dup(float a) {
    u64 r; asm("mov.b64 %0, {%1, %1};" : "=l"(r) : "f"(a)); return r;
}
__device__ __forceinline__ void unpack2(u64 v, float& lo, float& hi) {
    asm("mov.b64 {%0, %1}, %2;" : "=f"(lo), "=f"(hi) : "l"(v));
}
__device__ __forceinline__ void ffma2(u64& d, u64 a, u64 b) {
    asm("fma.rn.f32x2 %0, %1, %2, %3;" : "=l"(d) : "l"(a), "l"(b), "l"(d));
}

// ---------------- HMMA helpers (baseline PTX, legal on sm_103) ---------------
__device__ __forceinline__ void ldm4(u32* r, u32 a) {
    asm volatile("ldmatrix.sync.aligned.m8n8.x4.shared.b16 {%0,%1,%2,%3}, [%4];"
        : "=r"(r[0]), "=r"(r[1]), "=r"(r[2]), "=r"(r[3]) : "r"(a));
}
__device__ __forceinline__ void mma_bf16(float* c, const u32* a, const u32* b) {
    asm volatile("mma.sync.aligned.m16n8k16.row.col.f32.bf16.bf16.f32 "
        "{%0,%1,%2,%3}, {%4,%5,%6,%7}, {%8,%9}, {%0,%1,%2,%3};"
        : "+f"(c[0]), "+f"(c[1]), "+f"(c[2]), "+f"(c[3])
        : "r"(a[0]), "r"(a[1]), "r"(a[2]), "r"(a[3]), "r"(b[0]), "r"(b[1]));
}

// Tile geometry: 128 rows x 128 K-cols bf16, row stride 272B (17*16B -> ldmatrix
// rows land on distinct 16B lanes; conflict-free without swizzle).
#define RSTR   272
#define TILE   (128 * RSTR)        // 34816 B per tile
#define SMEM_G (4 * TILE + 1024)   // AH, AL, BH, BL + reduction tail

// Split fp32 -> bf16 hi + lo, store pairs into [row][c] tile (stride 272B).
__device__ __forceinline__ void split272(char* sm, int offH, int row, int c, float4 f) {
    int off = row * RSTR + c * 2;
    __nv_bfloat16 h0 = __float2bfloat16(f.x);
    __nv_bfloat16 h1 = __float2bfloat16(f.y);
    __nv_bfloat16 h2 = __float2bfloat16(f.z);
    __nv_bfloat16 h3 = __float2bfloat16(f.w);
    __nv_bfloat16 l0 = __float2bfloat16(f.x - __bfloat162float(h0));
    __nv_bfloat16 l1 = __float2bfloat16(f.y - __bfloat162float(h1));
    __nv_bfloat16 l2 = __float2bfloat16(f.z - __bfloat162float(h2));
    __nv_bfloat16 l3 = __float2bfloat16(f.w - __bfloat162float(h3));
    uint2 hp, lp;
    hp.x = (u32)__bfloat16_as_ushort(h0) | ((u32)__bfloat16_as_ushort(h1) << 16);
    hp.y = (u32)__bfloat16_as_ushort(h2) | ((u32)__bfloat16_as_ushort(h3) << 16);
    lp.x = (u32)__bfloat16_as_ushort(l0) | ((u32)__bfloat16_as_ushort(l1) << 16);
    lp.y = (u32)__bfloat16_as_ushort(l2) | ((u32)__bfloat16_as_ushort(l3) << 16);
    *(uint2*)(sm + offH + off) = hp;
    *(uint2*)(sm + offH + TILE + off) = lp;   // lo tile sits TILE bytes after hi
}

// Warp-tile compute: 128x128x128 per CTA, 8 warps (4 along M x 2 along N).
// Each warp: 32(M) x 64(N), split-bf16 3-term accumulate into acc[2][8][4].
__device__ __forceinline__ void warp_gemm128(
    u32 sA, u32 sB, int wy, int wx, int lane, float acc[2][8][4])
{
    // ldmatrix base addresses (per-lane row assignment, see fragment layouts)
    const u32 aBase = sA + (u32)((wy * 32 + (lane & 15)) * RSTR + ((lane >> 4) << 4));
    const u32 bBase = sB + (u32)((wx * 64 + ((lane >> 4) & 1) * 8 + (lane & 7)) * RSTR
                                 + (((lane >> 3) & 1) << 4));
#pragma unroll
    for (int ks = 0; ks < 8; ks++) {
        const u32 kb = ks * 32;
        u32 ah[2][4], al[2][4], bh[8][2], bl[8][2];
#pragma unroll
        for (int mt = 0; mt < 2; mt++) {
            ldm4(ah[mt], aBase + mt * (16 * RSTR) + kb);
            ldm4(al[mt], aBase + mt * (16 * RSTR) + kb + TILE);
        }
#pragma unroll
        for (int np = 0; np < 4; np++) {
            u32 t[4];
            ldm4(t, bBase + np * (16 * RSTR) + kb);
            bh[2 * np][0] = t[0]; bh[2 * np][1] = t[1];
            bh[2 * np + 1][0] = t[2]; bh[2 * np + 1][1] = t[3];
            ldm4(t, bBase + np * (16 * RSTR) + kb + TILE);
            bl[2 * np][0] = t[0]; bl[2 * np][1] = t[1];
            bl[2 * np + 1][0] = t[2]; bl[2 * np + 1][1] = t[3];
        }
#pragma unroll
        for (int mt = 0; mt < 2; mt++)
#pragma unroll
            for (int nt = 0; nt < 8; nt++) {
                mma_bf16(acc[mt][nt], ah[mt], bh[nt]);
                mma_bf16(acc[mt][nt], al[mt], bh[nt]);
                mma_bf16(acc[mt][nt], ah[mt], bl[nt]);
            }
    }
}

// =============================================================================
// Kernel 1: QKV. q,k written TRANSPOSED [b][n][c]; v natural [b][c][n].
// =============================================================================
__global__ __launch_bounds__(256) void qkv_kernel(
    const float* __restrict__ x,
    const float* __restrict__ Wq, const float* __restrict__ bq,
    const float* __restrict__ Wk, const float* __restrict__ bk,
    const float* __restrict__ Wv, const float* __restrict__ bv)
{
    __shared__ __align__(16) float xs[CH * 64];
    const int n0 = blockIdx.x * 64;
    const int b  = blockIdx.y;
    const int m  = blockIdx.z;
    const float* W    = (m == 0) ? Wq : ((m == 1) ? Wk : Wv);
    const float* bias = (m == 0) ? bq : ((m == 1) ? bk : bv);

    const int t = threadIdx.x;
    for (int idx = t; idx < CH * 64; idx += 256) {
        int ci = idx >> 6, nn = idx & 63;
        xs[idx] = x[(size_t)(b * CH + ci) * NPIX + n0 + nn];
    }
    __syncthreads();

    const int co0 = (t >> 3) << 2;
    const int nn0 = (t & 7) << 3;

    u64 acc[4][4];
#pragma unroll
    for (int u = 0; u < 4; u++)
#pragma unroll
        for (int v = 0; v < 4; v++) acc[u][v] = 0ull;

#pragma unroll 1
    for (int ci0 = 0; ci0 < CH; ci0 += 4) {
        float wr[4][4];
#pragma unroll
        for (int u = 0; u < 4; u++) {
            float4 f = *(const float4*)&W[(co0 + u) * CH + ci0];
            wr[u][0] = f.x; wr[u][1] = f.y; wr[u][2] = f.z; wr[u][3] = f.w;
        }
#pragma unroll
        for (int kk = 0; kk < 4; kk++) {
            const u64* xp = (const u64*)&xs[(ci0 + kk) * 64 + nn0];
            u64 x0 = xp[0], x1 = xp[1], x2 = xp[2], x3 = xp[3];
#pragma unroll
            for (int u = 0; u < 4; u++) {
                u64 a2 = pack_dup(wr[u][kk]);
                ffma2(acc[u][0], a2, x0);
                ffma2(acc[u][1], a2, x1);
                ffma2(acc[u][2], a2, x2);
                ffma2(acc[u][3], a2, x3);
            }
        }
    }

    float bs[4];
#pragma unroll
    for (int u = 0; u < 4; u++) bs[u] = bias[co0 + u];

    if (m == 2) {  // v: natural layout
#pragma unroll
        for (int u = 0; u < 4; u++) {
            size_t base = (size_t)(b * CH + co0 + u) * NPIX + n0 + nn0;
#pragma unroll
            for (int v = 0; v < 4; v++) {
                float o0, o1;
                unpack2(acc[u][v], o0, o1);
                g_v[base + 2 * v]     = o0 + bs[u];
                g_v[base + 2 * v + 1] = o1 + bs[u];
            }
        }
    } else {       // q,k: transposed [n][c]
        float* gT = (m == 0) ? g_qT : g_kT;
#pragma unroll
        for (int v = 0; v < 4; v++) {
            float o0[4], o1[4];
#pragma unroll
            for (int u = 0; u < 4; u++) unpack2(acc[u][v], o0[u], o1[u]);
            int n = n0 + nn0 + 2 * v;
            float4 w0 = make_float4(o0[0] + bs[0], o0[1] + bs[1], o0[2] + bs[2], o0[3] + bs[3]);
            float4 w1 = make_float4(o1[0] + bs[0], o1[1] + bs[1], o1[2] + bs[2], o1[3] + bs[3]);
            *(float4*)&gT[((size_t)b * NPIX + n) * CH + co0]     = w0;
            *(float4*)&gT[((size_t)b * NPIX + n + 1) * CH + co0] = w1;
        }
    }
}

// =============================================================================
// Kernel 2: energy via mma.sync split-bf16. E[i,j] = sum_c qT[i,c]*kT[j,c].
// Epilogue: p = exp(e) -> g_att, partial row sums -> g_psum (softmax-free).
// =============================================================================
__global__ __launch_bounds__(256, 1) void energy_hmma()
{
    extern __shared__ __align__(16) char sm[];
    const u32 sbase = (u32)__cvta_generic_to_shared(sm);
    float* wsum = (float*)(sm + 4 * TILE);   // [2][128]

    const int tid = threadIdx.x, warp = tid >> 5, lane = tid & 31;
    const int wy = warp & 3, wx = warp >> 2;
    const int j0 = blockIdx.x * 128, i0 = blockIdx.y * 128, b = blockIdx.z;

    // load + split q (A) and k (B) tiles, [row][c], coalesced float4
#pragma unroll
    for (int rep = 0; rep < 16; rep++) {
        int lin = rep * 256 + tid;
        int row = lin >> 5, c4 = (lin & 31) << 2;
        float4 fa = *(const float4*)&g_qT[((size_t)b * NPIX + i0 + row) * CH + c4];
        float4 fb = *(const float4*)&g_kT[((size_t)b * NPIX + j0 + row) * CH + c4];
        split272(sm, 0, row, c4, fa);
        split272(sm, 2 * TILE, row, c4, fb);
    }
    __syncthreads();

    float acc[2][8][4];
#pragma unroll
    for (int mt = 0; mt < 2; mt++)
#pragma unroll
        for (int nt = 0; nt < 8; nt++)
#pragma unroll
            for (int q = 0; q < 4; q++) acc[mt][nt][q] = 0.f;

    warp_gemm128(sbase, sbase + 2 * TILE, wy, wx, lane, acc);

    // epilogue: exp + store + per-row partial sums
    float rsum[2][2] = {{0.f, 0.f}, {0.f, 0.f}};
    const int colb = wx * 64 + 2 * (lane & 3);
#pragma unroll
    for (int mt = 0; mt < 2; mt++) {
        const int r0 = i0 + wy * 32 + mt * 16 + (lane >> 2);
        const size_t base0 = (size_t)b * NPIX * NPIX + (size_t)r0 * NPIX + j0;
        const size_t base1 = base0 + 8 * NPIX;
#pragma unroll
        for (int nt = 0; nt < 8; nt++) {
            float e0 = __expf(acc[mt][nt][0]);
            float e1 = __expf(acc[mt][nt][1]);
            float e2 = __expf(acc[mt][nt][2]);
            float e3 = __expf(acc[mt][nt][3]);
            rsum[mt][0] += e0 + e1;
            rsum[mt][1] += e2 + e3;
            *(float2*)&g_att[base0 + colb + nt * 8] = make_float2(e0, e1);
            *(float2*)&g_att[base1 + colb + nt * 8] = make_float2(e2, e3);
        }
    }
#pragma unroll
    for (int mt = 0; mt < 2; mt++)
#pragma unroll
        for (int h = 0; h < 2; h++) {
            float v = rsum[mt][h];
            v += __shfl_xor_sync(0xffffffffu, v, 1);
            v += __shfl_xor_sync(0xffffffffu, v, 2);
            if ((lane & 3) == 0)
                wsum[wx * 128 + wy * 32 + mt * 16 + h * 8 + (lane >> 2)] = v;
        }
    __syncthreads();
    if (tid < 128)
        g_psum[((size_t)b * NPIX + i0 + tid) * NJT + blockIdx.x] =
            wsum[tid] + wsum[128 + tid];
}

// =============================================================================
// Kernel 3: deterministic rowsum reduction (18 partials per row)
// =============================================================================
__global__ __launch_bounds__(256) void rowsum_kernel()
{
    int idx = blockIdx.x * 256 + threadIdx.x;
    if (idx < BATCH * NPIX) {
        const float* p = &g_psum[(size_t)idx * NJT];
        float s = 0.f;
#pragma unroll
        for (int t = 0; t < NJT; t++) s += p[t];
        g_rowsum[idx] = s;
    }
}

// =============================================================================
// Kernel 4a/4b: SE path
// =============================================================================
__global__ __launch_bounds__(256) void mean_kernel(const float* __restrict__ x)
{
    const int row = blockIdx.x;
    const float* p = x + (size_t)row * NPIX;
    const int t = threadIdx.x;
    float s = 0.f;
#pragma unroll
    for (int k = 0; k < 9; k++) s += p[t + k * 256];
#pragma unroll
    for (int o = 16; o > 0; o >>= 1) s += __shfl_xor_sync(0xffffffffu, s, o);
    __shared__ float red[8];
    if ((t & 31) == 0) red[t >> 5] = s;
    __syncthreads();
    if (t == 0) {
        float tot = red[0];
#pragma unroll
        for (int r = 1; r < 8; r++) tot += red[r];
        g_mean[row] = tot * (1.0f / (float)NPIX);
    }
}

__global__ __launch_bounds__(128) void se_kernel(
    const float* __restrict__ w1, const float* __restrict__ w2)
{
    __shared__ float hid[BATCH * (CH / RED)];
    const int t = threadIdx.x;
    if (t < 64) {
        int b = t >> 3, h = t & 7;
        float s = 0.f;
#pragma unroll 4
        for (int c = 0; c < CH; c++) s += g_mean[b * CH + c] * w1[h * CH + c];
        hid[t] = fmaxf(s, 0.f);
    }
    __syncthreads();
    for (int idx = t; idx < BATCH * CH; idx += 128) {
        int b = idx >> 7, c = idx & 127;
        float s = 0.f;
#pragma unroll
        for (int h = 0; h < 8; h++) s += hid[b * 8 + h] * w2[c * 8 + h];
        g_se[idx] = 1.0f / (1.0f + __expf(-s));
    }
}

// =============================================================================
// Kernel 5: out via mma.sync split-bf16. D[c,i] = sum_j v[c,j]*p[i,j], K=2304.
// Epilogue: /rowsum[i], *gamma, + x*se -> d_out.
// =============================================================================
__global__ __launch_bounds__(256, 1) void out_hmma(
    const float* __restrict__ x, const float* __restrict__ gamma,
    float* __restrict__ outp)
{
    extern __shared__ __align__(16) char sm[];
    const u32 sbase = (u32)__cvta_generic_to_shared(sm);
    float* rs = (float*)(sm + 4 * TILE);   // [128] reciprocal rowsums

    const int tid = threadIdx.x, warp = tid >> 5, lane = tid & 31;
    const int wy = warp & 3, wx = warp >> 2;
    const int i0 = blockIdx.x * 128, b = blockIdx.y;

    if (tid < 128) rs[tid] = 1.0f / g_rowsum[(size_t)b * NPIX + i0 + tid];

    float acc[2][8][4];
#pragma unroll
    for (int mt = 0; mt < 2; mt++)
#pragma unroll
        for (int nt = 0; nt < 8; nt++)
#pragma unroll
            for (int q = 0; q < 4; q++) acc[mt][nt][q] = 0.f;

#pragma unroll 1
    for (int jt = 0; jt < NJT; jt++) {
        const int j0 = jt * 128;
        float4 fa[2], fb[2];
#pragma unroll
        for (int h = 0; h < 2; h++) {   // 16 reps folded: 2 tiles x 8 reps each
            int lin = h * 2048;          // handled below in 8-step loop
            (void)lin; fa[h] = make_float4(0,0,0,0); fb[h] = fa[h];
        }
        __syncthreads();   // previous compute done before overwrite
#pragma unroll
        for (int rep = 0; rep < 16; rep++) {
            int lin = rep * 256 + tid;
            int row = lin >> 5, c4 = (lin & 31) << 2;
            float4 va = *(const float4*)&g_v[((size_t)b * CH + row) * NPIX + j0 + c4];
            float4 vb = *(const float4*)&g_att[((size_t)b * NPIX + i0 + row) * NPIX + j0 + c4];
            split272(sm, 0, row, c4, va);
            split272(sm, 2 * TILE, row, c4, vb);
        }
        __syncthreads();
        warp_gemm128(sbase, sbase + 2 * TILE, wy, wx, lane, acc);
    }

    // epilogue
    const float gam = gamma[0];
    const int colb = wx * 64 + 2 * (lane & 3);
#pragma unroll
    for (int mt = 0; mt < 2; mt++) {
        const int c0 = wy * 32 + mt * 16 + (lane >> 2);
        const int c1 = c0 + 8;
        const float se0 = g_se[b * CH + c0];
        const float se1 = g_se[b * CH + c1];
        const size_t ob0 = ((size_t)b * CH + c0) * NPIX + i0;
        const size_t ob1 = ((size_t)b * CH + c1) * NPIX + i0;
#pragma unroll
        for (int nt = 0; nt < 8; nt++) {
            const int ic = colb + nt * 8;
            const float r0 = rs[ic], r1 = rs[ic + 1];
            float2 x0 = *(const float2*)&x[ob0 + ic];
            float2 x1 = *(const float2*)&x[ob1 + ic];
            float2 o0, o1;
            o0.x = gam * (acc[mt][nt][0] * r0) + x0.x * se0;
            o0.y = gam * (acc[mt][nt][1] * r1) + x0.y * se0;
            o1.x = gam * (acc[mt][nt][2] * r0) + x1.x * se1;
            o1.y = gam * (acc[mt][nt][3] * r1) + x1.y * se1;
            *(float2*)&outp[ob0 + ic] = o0;
            *(float2*)&outp[ob1 + ic] = o1;
        }
    }
}

// =============================================================================
extern "C" void kernel_launch(void* const* d_in, const int* in_sizes, int n_in,
                              void* d_out, int out_size)
{
    const float* x     = (const float*)d_in[0];
    const float* Wq    = (const float*)d_in[1];
    const float* bq    = (const float*)d_in[2];
    const float* Wk    = (const float*)d_in[3];
    const float* bk    = (const float*)d_in[4];
    const float* Wv    = (const float*)d_in[5];
    const float* bv    = (const float*)d_in[6];
    const float* w1    = (const float*)d_in[7];
    const float* w2    = (const float*)d_in[8];
    const float* gamma = (const float*)d_in[9];
    float* out = (float*)d_out;

    cudaFuncSetAttribute(energy_hmma, cudaFuncAttributeMaxDynamicSharedMemorySize, SMEM_G);
    cudaFuncSetAttribute(out_hmma,    cudaFuncAttributeMaxDynamicSharedMemorySize, SMEM_G);

    qkv_kernel<<<dim3(NPIX / 64, BATCH, 3), 256>>>(x, Wq, bq, Wk, bk, Wv, bv);
    energy_hmma<<<dim3(NJT, NJT, BATCH), 256, SMEM_G>>>();
    rowsum_kernel<<<(BATCH * NPIX + 255) / 256, 256>>>();
    mean_kernel<<<BATCH * CH, 256>>>(x);
    se_kernel<<<1, 128>>>(w1, w2);
    out_hmma<<<dim3(NPIX / 128, BATCH), 256, SMEM_G>>>(x, gamma, out);
}

// round 9
// speedup vs baseline: 2.7096x; 1.5490x over previous
#include <cuda_runtime.h>
#include <cuda_bf16.h>

// Problem constants
#define BATCH 8
#define CH    128
#define NPIX  2304     // 48*48
#define RED   16
#define NJT   18       // NPIX/128

typedef unsigned long long u64;
typedef unsigned u32;

// ---------------- scratch (device globals; no allocation) --------------------
// Pre-split bf16 hi/lo planes produced by qkv.
__device__ __align__(16) __nv_bfloat16 g_qh[(size_t)BATCH * NPIX * CH]; // [b][n][c]
__device__ __align__(16) __nv_bfloat16 g_ql[(size_t)BATCH * NPIX * CH];
__device__ __align__(16) __nv_bfloat16 g_kh[(size_t)BATCH * NPIX * CH]; // [b][n][c]
__device__ __align__(16) __nv_bfloat16 g_kl[(size_t)BATCH * NPIX * CH];
__device__ __align__(16) __nv_bfloat16 g_vh[(size_t)BATCH * CH * NPIX]; // [b][c][j]
__device__ __align__(16) __nv_bfloat16 g_vl[(size_t)BATCH * CH * NPIX];
__device__ float g_mean[BATCH * CH];
__device__ float g_se[BATCH * CH];

// ---------------- f32x2 packed-math helpers (qkv) ----------------------------
__device__ __forceinline__ u64 pack_dup(float a) {
    u64 r; asm("mov.b64 %0, {%1, %1};" : "=l"(r) : "f"(a)); return r;
}
__device__ __forceinline__ void unpack2(u64 v, float& lo, float& hi) {
    asm("mov.b64 {%0, %1}, %2;" : "=f"(lo), "=f"(hi) : "l"(v));
}
__device__ __forceinline__ void ffma2(u64& d, u64 a, u64 b) {
    asm("fma.rn.f32x2 %0, %1, %2, %3;" : "=l"(d) : "l"(a), "l"(b), "l"(d));
}

// ---------------- HMMA / cp.async helpers (baseline PTX) ---------------------
__device__ __forceinline__ void ldm4(u32* r, u32 a) {
    asm volatile("ldmatrix.sync.aligned.m8n8.x4.shared.b16 {%0,%1,%2,%3}, [%4];"
        : "=r"(r[0]), "=r"(r[1]), "=r"(r[2]), "=r"(r[3]) : "r"(a));
}
__device__ __forceinline__ void mma_bf16(float* c, const u32* a, const u32* b) {
    asm volatile("mma.sync.aligned.m16n8k16.row.col.f32.bf16.bf16.f32 "
        "{%0,%1,%2,%3}, {%4,%5,%6,%7}, {%8,%9}, {%0,%1,%2,%3};"
        : "+f"(c[0]), "+f"(c[1]), "+f"(c[2]), "+f"(c[3])
        : "r"(a[0]), "r"(a[1]), "r"(a[2]), "r"(a[3]), "r"(b[0]), "r"(b[1]));
}
#define CP16(dst, src) \
    asm volatile("cp.async.cg.shared.global [%0], [%1], 16;" :: "r"(dst), "l"(src))
#define CPCOMMIT() asm volatile("cp.async.commit_group;" ::: "memory")
#define CPWAIT(n)  asm volatile("cp.async.wait_group %0;" :: "n"(n) : "memory")

// Tile: 128 rows x 128 bf16 cols, row stride 272B (17*16B -> ldmatrix rows hit
// distinct 16B lanes; conflict-free, R8-verified).
#define RSTR 272
#define TPL  (128 * RSTR)          // 34816 B
#define O_QH 0
#define O_QL (1 * TPL)
#define O_KH (2 * TPL)
#define O_KL (3 * TPL)
#define O_VH (4 * TPL)
#define O_VL (5 * TPL)
#define O_RS (6 * TPL)             // float[128] rowsums
#define SMEM_F (6 * TPL + 512)     // 209408 B

// Copy one 128x256B plane global->smem via cp.async (8 chunks per thread).
__device__ __forceinline__ void tile_cp(u32 smDst, const char* src,
                                        int rowBytes, int tid) {
#pragma unroll
    for (int rep = 0; rep < 8; rep++) {
        int id = rep * 256 + tid;
        int row = id >> 4, ch = (id & 15) << 4;
        CP16(smDst + row * RSTR + ch, src + (size_t)row * rowBytes + ch);
    }
}

__device__ __forceinline__ u32 packbf2(float a, float b) {
    __nv_bfloat162 t = __floats2bfloat162_rn(a, b);
    return *(u32*)&t;
}

// Split 4 floats into bf16 hi+lo, write 8B to each plane.
__device__ __forceinline__ void split4_store(__nv_bfloat16* ph, __nv_bfloat16* pl,
                                             size_t idx, float a, float b,
                                             float c, float d) {
    __nv_bfloat16 h0 = __float2bfloat16(a), h1 = __float2bfloat16(b);
    __nv_bfloat16 h2 = __float2bfloat16(c), h3 = __float2bfloat16(d);
    float l0 = a - __bfloat162float(h0), l1 = b - __bfloat162float(h1);
    float l2 = c - __bfloat162float(h2), l3 = d - __bfloat162float(h3);
    uint2 hp, lp;
    hp.x = (u32)__bfloat16_as_ushort(h0) | ((u32)__bfloat16_as_ushort(h1) << 16);
    hp.y = (u32)__bfloat16_as_ushort(h2) | ((u32)__bfloat16_as_ushort(h3) << 16);
    lp.x = packbf2(l0, l1);
    lp.y = packbf2(l2, l3);
    *(uint2*)(ph + idx) = hp;
    *(uint2*)(pl + idx) = lp;
}

// =============================================================================
// Kernel 1: QKV. Emits pre-split bf16 planes: q,k transposed [b][n][c],
// v natural [b][c][j].
// =============================================================================
__global__ __launch_bounds__(256) void qkv_kernel(
    const float* __restrict__ x,
    const float* __restrict__ Wq, const float* __restrict__ bq,
    const float* __restrict__ Wk, const float* __restrict__ bk,
    const float* __restrict__ Wv, const float* __restrict__ bv)
{
    __shared__ __align__(16) float xs[CH * 64];
    const int n0 = blockIdx.x * 64;
    const int b  = blockIdx.y;
    const int m  = blockIdx.z;
    const float* W    = (m == 0) ? Wq : ((m == 1) ? Wk : Wv);
    const float* bias = (m == 0) ? bq : ((m == 1) ? bk : bv);

    const int t = threadIdx.x;
    for (int idx = t; idx < CH * 64; idx += 256) {
        int ci = idx >> 6, nn = idx & 63;
        xs[idx] = x[(size_t)(b * CH + ci) * NPIX + n0 + nn];
    }
    __syncthreads();

    const int co0 = (t >> 3) << 2;
    const int nn0 = (t & 7) << 3;

    u64 acc[4][4];
#pragma unroll
    for (int u = 0; u < 4; u++)
#pragma unroll
        for (int v = 0; v < 4; v++) acc[u][v] = 0ull;

#pragma unroll 1
    for (int ci0 = 0; ci0 < CH; ci0 += 4) {
        float wr[4][4];
#pragma unroll
        for (int u = 0; u < 4; u++) {
            float4 f = *(const float4*)&W[(co0 + u) * CH + ci0];
            wr[u][0] = f.x; wr[u][1] = f.y; wr[u][2] = f.z; wr[u][3] = f.w;
        }
#pragma unroll
        for (int kk = 0; kk < 4; kk++) {
            const u64* xp = (const u64*)&xs[(ci0 + kk) * 64 + nn0];
            u64 x0 = xp[0], x1 = xp[1], x2 = xp[2], x3 = xp[3];
#pragma unroll
            for (int u = 0; u < 4; u++) {
                u64 a2 = pack_dup(wr[u][kk]);
                ffma2(acc[u][0], a2, x0);
                ffma2(acc[u][1], a2, x1);
                ffma2(acc[u][2], a2, x2);
                ffma2(acc[u][3], a2, x3);
            }
        }
    }

    float bs[4];
#pragma unroll
    for (int u = 0; u < 4; u++) bs[u] = bias[co0 + u];

    if (m == 2) {  // v: [b][c][j]
#pragma unroll
        for (int u = 0; u < 4; u++) {
            size_t base = (size_t)(b * CH + co0 + u) * NPIX + n0 + nn0;
            float f[8];
#pragma unroll
            for (int v = 0; v < 4; v++) {
                unpack2(acc[u][v], f[2 * v], f[2 * v + 1]);
                f[2 * v] += bs[u]; f[2 * v + 1] += bs[u];
            }
            split4_store(g_vh, g_vl, base,     f[0], f[1], f[2], f[3]);
            split4_store(g_vh, g_vl, base + 4, f[4], f[5], f[6], f[7]);
        }
    } else {       // q,k: [b][n][c]
        __nv_bfloat16* ph = (m == 0) ? g_qh : g_kh;
        __nv_bfloat16* pl = (m == 0) ? g_ql : g_kl;
#pragma unroll
        for (int v = 0; v < 4; v++) {
            float o0[4], o1[4];
#pragma unroll
            for (int u = 0; u < 4; u++) {
                unpack2(acc[u][v], o0[u], o1[u]);
                o0[u] += bs[u]; o1[u] += bs[u];
            }
            int n = n0 + nn0 + 2 * v;
            split4_store(ph, pl, ((size_t)b * NPIX + n) * CH + co0,
                         o0[0], o0[1], o0[2], o0[3]);
            split4_store(ph, pl, ((size_t)b * NPIX + n + 1) * CH + co0,
                         o1[0], o1[1], o1[2], o1[3]);
        }
    }
}

// =============================================================================
// Kernel 2a/2b: SE path (unchanged)
// =============================================================================
__global__ __launch_bounds__(256) void mean_kernel(const float* __restrict__ x)
{
    const int row = blockIdx.x;
    const float* p = x + (size_t)row * NPIX;
    const int t = threadIdx.x;
    float s = 0.f;
#pragma unroll
    for (int k = 0; k < 9; k++) s += p[t + k * 256];
#pragma unroll
    for (int o = 16; o > 0; o >>= 1) s += __shfl_xor_sync(0xffffffffu, s, o);
    __shared__ float red[8];
    if ((t & 31) == 0) red[t >> 5] = s;
    __syncthreads();
    if (t == 0) {
        float tot = red[0];
#pragma unroll
        for (int r = 1; r < 8; r++) tot += red[r];
        g_mean[row] = tot * (1.0f / (float)NPIX);
    }
}

__global__ __launch_bounds__(128) void se_kernel(
    const float* __restrict__ w1, const float* __restrict__ w2)
{
    __shared__ float hid[BATCH * (CH / RED)];
    const int t = threadIdx.x;
    if (t < 64) {
        int b = t >> 3, h = t & 7;
        float s = 0.f;
#pragma unroll 4
        for (int c = 0; c < CH; c++) s += g_mean[b * CH + c] * w1[h * CH + c];
        hid[t] = fmaxf(s, 0.f);
    }
    __syncthreads();
    for (int idx = t; idx < BATCH * CH; idx += 128) {
        int b = idx >> 7, c = idx & 127;
        float s = 0.f;
#pragma unroll
        for (int h = 0; h < 8; h++) s += hid[b * 8 + h] * w2[c * 8 + h];
        g_se[idx] = 1.0f / (1.0f + __expf(-s));
    }
}

// =============================================================================
// Kernel 3: fused attention. Per CTA: one (b, i-tile of 128). Streams 18
// j-tiles: S = q.kT (split bf16, 3 terms), p = exp(S) repacked in registers,
// out += p.vT (3 terms). Rowsum accumulated in registers. Epilogue:
// smem transpose + /rowsum *gamma + x*se -> d_out. cp.async pipelined.
// =============================================================================
__global__ __launch_bounds__(256) void fused_attn(
    const float* __restrict__ x, const float* __restrict__ gamma,
    float* __restrict__ outp)
{
    extern __shared__ __align__(16) char sm[];
    const u32 sb = (u32)__cvta_generic_to_shared(sm);
    const int tid = threadIdx.x, warp = tid >> 5, lane = tid & 31;
    const int i0 = blockIdx.x * 128, b = blockIdx.y;

    // global plane bases (bytes)
    const char* qh = (const char*)(g_qh + ((size_t)b * NPIX + i0) * CH);
    const char* ql = (const char*)(g_ql + ((size_t)b * NPIX + i0) * CH);
    const char* kh = (const char*)(g_kh + (size_t)b * NPIX * CH);
    const char* kl = (const char*)(g_kl + (size_t)b * NPIX * CH);
    const char* vh = (const char*)(g_vh + (size_t)b * CH * NPIX);
    const char* vl = (const char*)(g_vl + (size_t)b * CH * NPIX);
    const int KROW = CH * 2;       // 256 B per q/k row
    const int VROW = NPIX * 2;     // 4608 B per v row

    // prologue: q, k(0), v(0)
    tile_cp(sb + O_QH, qh, KROW, tid);
    tile_cp(sb + O_QL, ql, KROW, tid);
    CPCOMMIT();
    tile_cp(sb + O_KH, kh, KROW, tid);
    tile_cp(sb + O_KL, kl, KROW, tid);
    CPCOMMIT();
    tile_cp(sb + O_VH, vh, VROW, tid);
    tile_cp(sb + O_VL, vl, VROW, tid);
    CPCOMMIT();
    CPWAIT(1);          // q + k(0) arrived; v(0) may be in flight
    __syncthreads();

    // ldmatrix bases (R8-verified lane formulas)
    const u32 aQ = sb + O_QH + (u32)((warp * 16 + (lane & 15)) * RSTR
                                     + ((lane >> 4) << 4));
    const u32 rB = (u32)(((((lane >> 4) & 1) << 3) + (lane & 7)) * RSTR
                         + (((lane >> 3) & 1) << 4));
    const u32 bK = sb + O_KH + rB;
    const u32 bV = sb + O_VH + rB;

    float accO[16][4];
#pragma unroll
    for (int nt = 0; nt < 16; nt++)
#pragma unroll
        for (int q = 0; q < 4; q++) accO[nt][q] = 0.f;
    float rs0 = 0.f, rs1 = 0.f;

#pragma unroll 1
    for (int jt = 0; jt < NJT; jt++) {
        // ---- S = q . k^T ----
        float accS[16][4];
#pragma unroll
        for (int nt = 0; nt < 16; nt++)
#pragma unroll
            for (int q = 0; q < 4; q++) accS[nt][q] = 0.f;
#pragma unroll
        for (int ks = 0; ks < 8; ks++) {
            u32 ah[4], al[4];
            ldm4(ah, aQ + ks * 32);
            ldm4(al, aQ + ks * 32 + TPL);
#pragma unroll
            for (int np = 0; np < 8; np++) {
                u32 bh[4], bl[4];
                ldm4(bh, bK + np * (16 * RSTR) + ks * 32);
                ldm4(bl, bK + np * (16 * RSTR) + ks * 32 + TPL);
                mma_bf16(accS[2 * np],     ah, bh);
                mma_bf16(accS[2 * np],     al, bh);
                mma_bf16(accS[2 * np],     ah, bl);
                mma_bf16(accS[2 * np + 1], ah, bh + 2);
                mma_bf16(accS[2 * np + 1], al, bh + 2);
                mma_bf16(accS[2 * np + 1], ah, bl + 2);
            }
        }
        CPWAIT(0);          // v(jt) arrived; also all warps past S before k overwrite
        __syncthreads();
        if (jt + 1 < NJT) {
            tile_cp(sb + O_KH, kh + (size_t)(jt + 1) * 128 * KROW, KROW, tid);
            tile_cp(sb + O_KL, kl + (size_t)(jt + 1) * 128 * KROW, KROW, tid);
            CPCOMMIT();
        }

        // ---- p = exp(S), repack into A fragments (hi/lo) ----
        u32 pa[8][4], pb[8][4];
#pragma unroll
        for (int ks = 0; ks < 8; ks++) {
#pragma unroll
            for (int h = 0; h < 2; h++) {
                const int nt = 2 * ks + h;
                float e0 = __expf(accS[nt][0]);
                float e1 = __expf(accS[nt][1]);
                float e2 = __expf(accS[nt][2]);
                float e3 = __expf(accS[nt][3]);
                rs0 += e0 + e1; rs1 += e2 + e3;
                __nv_bfloat16 h0 = __float2bfloat16(e0), h1 = __float2bfloat16(e1);
                __nv_bfloat16 h2 = __float2bfloat16(e2), h3 = __float2bfloat16(e3);
                pa[ks][2 * h]     = (u32)__bfloat16_as_ushort(h0)
                                  | ((u32)__bfloat16_as_ushort(h1) << 16);
                pa[ks][2 * h + 1] = (u32)__bfloat16_as_ushort(h2)
                                  | ((u32)__bfloat16_as_ushort(h3) << 16);
                pb[ks][2 * h]     = packbf2(e0 - __bfloat162float(h0),
                                            e1 - __bfloat162float(h1));
                pb[ks][2 * h + 1] = packbf2(e2 - __bfloat162float(h2),
                                            e3 - __bfloat162float(h3));
            }
        }

        // ---- out += p . v^T ----
#pragma unroll
        for (int ks = 0; ks < 8; ks++) {
#pragma unroll
            for (int np = 0; np < 8; np++) {
                u32 wh[4], wl[4];
                ldm4(wh, bV + np * (16 * RSTR) + ks * 32);
                ldm4(wl, bV + np * (16 * RSTR) + ks * 32 + TPL);
                mma_bf16(accO[2 * np],     pa[ks], wh);
                mma_bf16(accO[2 * np],     pb[ks], wh);
                mma_bf16(accO[2 * np],     pa[ks], wl);
                mma_bf16(accO[2 * np + 1], pa[ks], wh + 2);
                mma_bf16(accO[2 * np + 1], pb[ks], wh + 2);
                mma_bf16(accO[2 * np + 1], pa[ks], wl + 2);
            }
        }
        CPWAIT(0);          // k(jt+1) arrived; v buffer free
        __syncthreads();
        if (jt + 1 < NJT) {
            tile_cp(sb + O_VH, vh + (size_t)(jt + 1) * 256, VROW, tid);
            tile_cp(sb + O_VL, vl + (size_t)(jt + 1) * 256, VROW, tid);
            CPCOMMIT();
        }
    }

    // ---- rowsum reduce (quad shuffle) -> smem ----
    float* rssm = (float*)(sm + O_RS);
    rs0 += __shfl_xor_sync(0xffffffffu, rs0, 1);
    rs0 += __shfl_xor_sync(0xffffffffu, rs0, 2);
    rs1 += __shfl_xor_sync(0xffffffffu, rs1, 1);
    rs1 += __shfl_xor_sync(0xffffffffu, rs1, 2);
    if ((lane & 3) == 0) {
        rssm[warp * 16 + (lane >> 2)]     = rs0;
        rssm[warp * 16 + 8 + (lane >> 2)] = rs1;
    }

    // ---- transpose accO (Dt[i][c]) -> trans[c][i] in smem (reuse q region) ----
    float* trans = (float*)sm;                 // 128 x 132 floats = 67.6 KB
    __syncthreads();
    {
        const int r = lane >> 2, c0 = 2 * (lane & 3);
        const int iA = warp * 16 + r, iB = iA + 8;
#pragma unroll
        for (int nt = 0; nt < 16; nt++) {
            const int c = nt * 8 + c0;
            trans[c * 132 + iA]       = accO[nt][0];
            trans[(c + 1) * 132 + iA] = accO[nt][1];
            trans[c * 132 + iB]       = accO[nt][2];
            trans[(c + 1) * 132 + iB] = accO[nt][3];
        }
    }
    __syncthreads();

    // ---- coalesced epilogue: /rowsum *gamma + x*se ----
    const float gam = gamma[0];
    float4 rsv = *(float4*)&rssm[lane * 4];
    const float4 ri = make_float4(1.f / rsv.x, 1.f / rsv.y, 1.f / rsv.z, 1.f / rsv.w);
#pragma unroll
    for (int r = 0; r < 16; r++) {
        const int c = warp * 16 + r;
        const float sec = g_se[b * CH + c];
        const size_t base = (size_t)(b * CH + c) * NPIX + i0 + lane * 4;
        float4 tv = *(float4*)&trans[c * 132 + lane * 4];
        float4 xv = *(const float4*)&x[base];
        float4 o;
        o.x = gam * (tv.x * ri.x) + xv.x * sec;
        o.y = gam * (tv.y * ri.y) + xv.y * sec;
        o.z = gam * (tv.z * ri.z) + xv.z * sec;
        o.w = gam * (tv.w * ri.w) + xv.w * sec;
        *(float4*)&outp[base] = o;
    }
}

// =============================================================================
extern "C" void kernel_launch(void* const* d_in, const int* in_sizes, int n_in,
                              void* d_out, int out_size)
{
    const float* x     = (const float*)d_in[0];
    const float* Wq    = (const float*)d_in[1];
    const float* bq    = (const float*)d_in[2];
    const float* Wk    = (const float*)d_in[3];
    const float* bk    = (const float*)d_in[4];
    const float* Wv    = (const float*)d_in[5];
    const float* bv    = (const float*)d_in[6];
    const float* w1    = (const float*)d_in[7];
    const float* w2    = (const float*)d_in[8];
    const float* gamma = (const float*)d_in[9];
    float* out = (float*)d_out;

    cudaFuncSetAttribute(fused_attn, cudaFuncAttributeMaxDynamicSharedMemorySize,
                         SMEM_F);

    qkv_kernel<<<dim3(NPIX / 64, BATCH, 3), 256>>>(x, Wq, bq, Wk, bk, Wv, bv);
    mean_kernel<<<BATCH * CH, 256>>>(x);
    se_kernel<<<1, 128>>>(w1, w2);
    fused_attn<<<dim3(NJT, BATCH), 256, SMEM_F>>>(x, gamma, out);
}

// round 11
// speedup vs baseline: 2.7355x; 1.0095x over previous
#include <cuda_runtime.h>
#include <cuda_bf16.h>

// Problem constants
#define BATCH 8
#define CH    128
#define NPIX  2304     // 48*48
#define RED   16
#define NIT   36       // NPIX/64 i-tiles
#define NJS   36       // NPIX/64 j-steps

typedef unsigned long long u64;
typedef unsigned u32;

// ---------------- scratch (device globals; no allocation) --------------------
__device__ __align__(16) __nv_bfloat16 g_qh[(size_t)BATCH * NPIX * CH]; // [b][n][c]
__device__ __align__(16) __nv_bfloat16 g_ql[(size_t)BATCH * NPIX * CH];
__device__ __align__(16) __nv_bfloat16 g_kh[(size_t)BATCH * NPIX * CH]; // [b][n][c]
__device__ __align__(16) __nv_bfloat16 g_kl[(size_t)BATCH * NPIX * CH];
__device__ __align__(16) __nv_bfloat16 g_vh[(size_t)BATCH * CH * NPIX]; // [b][c][j]
__device__ __align__(16) __nv_bfloat16 g_vl[(size_t)BATCH * CH * NPIX];
__device__ float g_mean[BATCH * CH];
__device__ float g_se[BATCH * CH];

// ---------------- f32x2 packed-math helpers (qkv) ----------------------------
__device__ __forceinline__ u64 pack_dup(float a) {
    u64 r; asm("mov.b64 %0, {%1, %1};" : "=l"(r) : "f"(a)); return r;
}
__device__ __forceinline__ void unpack2(u64 v, float& lo, float& hi) {
    asm("mov.b64 {%0, %1}, %2;" : "=f"(lo), "=f"(hi) : "l"(v));
}
__device__ __forceinline__ void ffma2(u64& d, u64 a, u64 b) {
    asm("fma.rn.f32x2 %0, %1, %2, %3;" : "=l"(d) : "l"(a), "l"(b), "l"(d));
}

// ---------------- HMMA / cp.async helpers ------------------------------------
__device__ __forceinline__ void ldm4(u32* r, u32 a) {
    asm volatile("ldmatrix.sync.aligned.m8n8.x4.shared.b16 {%0,%1,%2,%3}, [%4];"
        : "=r"(r[0]), "=r"(r[1]), "=r"(r[2]), "=r"(r[3]) : "r"(a));
}
__device__ __forceinline__ void mma_bf16(float* c, const u32* a, const u32* b) {
    asm volatile("mma.sync.aligned.m16n8k16.row.col.f32.bf16.bf16.f32 "
        "{%0,%1,%2,%3}, {%4,%5,%6,%7}, {%8,%9}, {%0,%1,%2,%3};"
        : "+f"(c[0]), "+f"(c[1]), "+f"(c[2]), "+f"(c[3])
        : "r"(a[0]), "r"(a[1]), "r"(a[2]), "r"(a[3]), "r"(b[0]), "r"(b[1]));
}
#define CP16(dst, src) \
    asm volatile("cp.async.cg.shared.global [%0], [%1], 16;" :: "r"(dst), "l"(src))
#define CPCOMMIT() asm volatile("cp.async.commit_group;" ::: "memory")
#define CPWAIT(n)  asm volatile("cp.async.wait_group %0;" :: "n"(n) : "memory")

// q/k tiles: 64 rows x 128 bf16 (256B data), stride 272B (conflict-free).
// v tile:  128 rows x  64 bf16 (128B data), stride 144B (odd*16B -> conflict-free).
#define RSQK 272
#define RSV  144
#define TQK  (64 * RSQK)           // 17408 B per plane
#define TV   (128 * RSV)           // 18432 B per plane
#define O_QH 0
#define O_QL (O_QH + TQK)
#define O_KH (O_QL + TQK)
#define O_KL (O_KH + TQK)
#define O_VH (O_KL + TQK)
#define O_VL (O_VH + TV)
#define O_RS (O_VL + TV)           // float[64] rowsums
#define SMEM_F (O_RS + 256)        // 104704 B -> 2 CTAs/SM

__device__ __forceinline__ u32 packbf2(float a, float b) {
    __nv_bfloat162 t = __floats2bfloat162_rn(a, b);
    return *(u32*)&t;
}

__device__ __forceinline__ void split4_store(__nv_bfloat16* ph, __nv_bfloat16* pl,
                                             size_t idx, float a, float b,
                                             float c, float d) {
    __nv_bfloat16 h0 = __float2bfloat16(a), h1 = __float2bfloat16(b);
    __nv_bfloat16 h2 = __float2bfloat16(c), h3 = __float2bfloat16(d);
    float l0 = a - __bfloat162float(h0), l1 = b - __bfloat162float(h1);
    float l2 = c - __bfloat162float(h2), l3 = d - __bfloat162float(h3);
    uint2 hp, lp;
    hp.x = (u32)__bfloat16_as_ushort(h0) | ((u32)__bfloat16_as_ushort(h1) << 16);
    hp.y = (u32)__bfloat16_as_ushort(h2) | ((u32)__bfloat16_as_ushort(h3) << 16);
    lp.x = packbf2(l0, l1);
    lp.y = packbf2(l2, l3);
    *(uint2*)(ph + idx) = hp;
    *(uint2*)(pl + idx) = lp;
}

// Copy 64 rows x 256B (q/k plane) via cp.async, 128 threads.
__device__ __forceinline__ void cp_qk(u32 dst, const char* src, int tid) {
#pragma unroll
    for (int rep = 0; rep < 8; rep++) {
        int id = rep * 128 + tid;
        int row = id >> 4, ch = (id & 15) << 4;
        CP16(dst + row * RSQK + ch, src + row * 256 + ch);
    }
}
// Copy 128 rows x 128B (v plane, global row stride 4608B), 128 threads.
__device__ __forceinline__ void cp_v(u32 dst, const char* src, int tid) {
#pragma unroll
    for (int rep = 0; rep < 8; rep++) {
        int id = rep * 128 + tid;
        int row = id >> 3, ch = (id & 7) << 4;
        CP16(dst + row * RSV + ch, src + (size_t)row * 4608 + ch);
    }
}

// =============================================================================
// Kernel 1: QKV. Emits pre-split bf16 planes: q,k [b][n][c], v [b][c][j].
// =============================================================================
__global__ __launch_bounds__(256) void qkv_kernel(
    const float* __restrict__ x,
    const float* __restrict__ Wq, const float* __restrict__ bq,
    const float* __restrict__ Wk, const float* __restrict__ bk,
    const float* __restrict__ Wv, const float* __restrict__ bv)
{
    __shared__ __align__(16) float xs[CH * 64];
    const int n0 = blockIdx.x * 64;
    const int b  = blockIdx.y;
    const int m  = blockIdx.z;
    const float* W    = (m == 0) ? Wq : ((m == 1) ? Wk : Wv);
    const float* bias = (m == 0) ? bq : ((m == 1) ? bk : bv);

    const int t = threadIdx.x;
    for (int idx = t; idx < CH * 64; idx += 256) {
        int ci = idx >> 6, nn = idx & 63;
        xs[idx] = x[(size_t)(b * CH + ci) * NPIX + n0 + nn];
    }
    __syncthreads();

    const int co0 = (t >> 3) << 2;
    const int nn0 = (t & 7) << 3;

    u64 acc[4][4];
#pragma unroll
    for (int u = 0; u < 4; u++)
#pragma unroll
        for (int v = 0; v < 4; v++) acc[u][v] = 0ull;

#pragma unroll 1
    for (int ci0 = 0; ci0 < CH; ci0 += 4) {
        float wr[4][4];
#pragma unroll
        for (int u = 0; u < 4; u++) {
            float4 f = *(const float4*)&W[(co0 + u) * CH + ci0];
            wr[u][0] = f.x; wr[u][1] = f.y; wr[u][2] = f.z; wr[u][3] = f.w;
        }
#pragma unroll
        for (int kk = 0; kk < 4; kk++) {
            const u64* xp = (const u64*)&xs[(ci0 + kk) * 64 + nn0];
            u64 x0 = xp[0], x1 = xp[1], x2 = xp[2], x3 = xp[3];
#pragma unroll
            for (int u = 0; u < 4; u++) {
                u64 a2 = pack_dup(wr[u][kk]);
                ffma2(acc[u][0], a2, x0);
                ffma2(acc[u][1], a2, x1);
                ffma2(acc[u][2], a2, x2);
                ffma2(acc[u][3], a2, x3);
            }
        }
    }

    float bs[4];
#pragma unroll
    for (int u = 0; u < 4; u++) bs[u] = bias[co0 + u];

    if (m == 2) {  // v: [b][c][j]
#pragma unroll
        for (int u = 0; u < 4; u++) {
            size_t base = (size_t)(b * CH + co0 + u) * NPIX + n0 + nn0;
            float f[8];
#pragma unroll
            for (int v = 0; v < 4; v++) {
                unpack2(acc[u][v], f[2 * v], f[2 * v + 1]);
                f[2 * v] += bs[u]; f[2 * v + 1] += bs[u];
            }
            split4_store(g_vh, g_vl, base,     f[0], f[1], f[2], f[3]);
            split4_store(g_vh, g_vl, base + 4, f[4], f[5], f[6], f[7]);
        }
    } else {       // q,k: [b][n][c]
        __nv_bfloat16* ph = (m == 0) ? g_qh : g_kh;
        __nv_bfloat16* pl = (m == 0) ? g_ql : g_kl;
#pragma unroll
        for (int v = 0; v < 4; v++) {
            float o0[4], o1[4];
#pragma unroll
            for (int u = 0; u < 4; u++) {
                unpack2(acc[u][v], o0[u], o1[u]);
                o0[u] += bs[u]; o1[u] += bs[u];
            }
            int n = n0 + nn0 + 2 * v;
            split4_store(ph, pl, ((size_t)b * NPIX + n) * CH + co0,
                         o0[0], o0[1], o0[2], o0[3]);
            split4_store(ph, pl, ((size_t)b * NPIX + n + 1) * CH + co0,
                         o1[0], o1[1], o1[2], o1[3]);
        }
    }
}

// =============================================================================
// Kernel 2a/2b: SE path (unchanged)
// =============================================================================
__global__ __launch_bounds__(256) void mean_kernel(const float* __restrict__ x)
{
    const int row = blockIdx.x;
    const float* p = x + (size_t)row * NPIX;
    const int t = threadIdx.x;
    float s = 0.f;
#pragma unroll
    for (int k = 0; k < 9; k++) s += p[t + k * 256];
#pragma unroll
    for (int o = 16; o > 0; o >>= 1) s += __shfl_xor_sync(0xffffffffu, s, o);
    __shared__ float red[8];
    if ((t & 31) == 0) red[t >> 5] = s;
    __syncthreads();
    if (t == 0) {
        float tot = red[0];
#pragma unroll
        for (int r = 1; r < 8; r++) tot += red[r];
        g_mean[row] = tot * (1.0f / (float)NPIX);
    }
}

__global__ __launch_bounds__(128) void se_kernel(
    const float* __restrict__ w1, const float* __restrict__ w2)
{
    __shared__ float hid[BATCH * (CH / RED)];
    const int t = threadIdx.x;
    if (t < 64) {
        int b = t >> 3, h = t & 7;
        float s = 0.f;
#pragma unroll 4
        for (int c = 0; c < CH; c++) s += g_mean[b * CH + c] * w1[h * CH + c];
        hid[t] = fmaxf(s, 0.f);
    }
    __syncthreads();
    for (int idx = t; idx < BATCH * CH; idx += 128) {
        int b = idx >> 7, c = idx & 127;
        float s = 0.f;
#pragma unroll
        for (int h = 0; h < 8; h++) s += hid[b * 8 + h] * w2[c * 8 + h];
        g_se[idx] = 1.0f / (1.0f + __expf(-s));
    }
}

// =============================================================================
// Kernel 3: fused attention, occupancy-2 variant.
// CTA = 128 threads / 4 warps, i-tile 64 (warp owns 16 rows), j-steps of 64.
// S = q.kT (3-term split), p = exp(S) repacked in regs, out += p.vT (3 terms).
// =============================================================================
__global__ __launch_bounds__(128, 2) void fused_attn(
    const float* __restrict__ x, const float* __restrict__ gamma,
    float* __restrict__ outp)
{
    extern __shared__ __align__(16) char sm[];
    const u32 sb = (u32)__cvta_generic_to_shared(sm);
    const int tid = threadIdx.x, warp = tid >> 5, lane = tid & 31;
    const int i0 = blockIdx.x * 64, b = blockIdx.y;

    const char* qh = (const char*)(g_qh + ((size_t)b * NPIX + i0) * CH);
    const char* ql = (const char*)(g_ql + ((size_t)b * NPIX + i0) * CH);
    const char* kh = (const char*)(g_kh + (size_t)b * NPIX * CH);
    const char* kl = (const char*)(g_kl + (size_t)b * NPIX * CH);
    const char* vh = (const char*)(g_vh + (size_t)b * CH * NPIX);
    const char* vl = (const char*)(g_vl + (size_t)b * CH * NPIX);

    // prologue: q, k(0), v(0)
    cp_qk(sb + O_QH, qh, tid);
    cp_qk(sb + O_QL, ql, tid);
    CPCOMMIT();
    cp_qk(sb + O_KH, kh, tid);
    cp_qk(sb + O_KL, kl, tid);
    CPCOMMIT();
    cp_v(sb + O_VH, vh, tid);
    cp_v(sb + O_VL, vl, tid);
    CPCOMMIT();
    CPWAIT(1);
    __syncthreads();

    // ldmatrix bases
    const u32 aQ = sb + O_QH + (u32)((warp * 16 + (lane & 15)) * RSQK
                                     + ((lane >> 4) << 4));
    const u32 bK = sb + O_KH + (u32)(((((lane >> 4) & 1) << 3) + (lane & 7)) * RSQK
                                     + (((lane >> 3) & 1) << 4));
    const u32 bV = sb + O_VH + (u32)(((((lane >> 4) & 1) << 3) + (lane & 7)) * RSV
                                     + (((lane >> 3) & 1) << 4));

    float accO[16][4];
#pragma unroll
    for (int nt = 0; nt < 16; nt++)
#pragma unroll
        for (int q = 0; q < 4; q++) accO[nt][q] = 0.f;
    float rs0 = 0.f, rs1 = 0.f;

#pragma unroll 1
    for (int jt = 0; jt < NJS; jt++) {
        // ---- S = q . k^T  (M=16/warp, N=64, K=128) ----
        float accS[8][4];
#pragma unroll
        for (int nt = 0; nt < 8; nt++)
#pragma unroll
            for (int q = 0; q < 4; q++) accS[nt][q] = 0.f;
#pragma unroll
        for (int ks = 0; ks < 8; ks++) {
            u32 ah[4], al[4];
            ldm4(ah, aQ + ks * 32);
            ldm4(al, aQ + ks * 32 + TQK);
#pragma unroll
            for (int np = 0; np < 4; np++) {
                u32 bh[4], bl[4];
                ldm4(bh, bK + np * (16 * RSQK) + ks * 32);
                ldm4(bl, bK + np * (16 * RSQK) + ks * 32 + TQK);
                mma_bf16(accS[2 * np],     ah, bh);
                mma_bf16(accS[2 * np],     al, bh);
                mma_bf16(accS[2 * np],     ah, bl);
                mma_bf16(accS[2 * np + 1], ah, bh + 2);
                mma_bf16(accS[2 * np + 1], al, bh + 2);
                mma_bf16(accS[2 * np + 1], ah, bl + 2);
            }
        }
        CPWAIT(0);          // v(jt) arrived
        __syncthreads();    // all warps past k(jt) reads
        if (jt + 1 < NJS) {
            cp_qk(sb + O_KH, kh + (size_t)(jt + 1) * 64 * 256, tid);
            cp_qk(sb + O_KL, kl + (size_t)(jt + 1) * 64 * 256, tid);
            CPCOMMIT();
        }

        // ---- p = exp(S) repacked into A fragments (hi/lo), K=64 -> 4 ks ----
        u32 pa[4][4], pb[4][4];
#pragma unroll
        for (int ks = 0; ks < 4; ks++) {
#pragma unroll
            for (int h = 0; h < 2; h++) {
                const int nt = 2 * ks + h;
                float e0 = __expf(accS[nt][0]);
                float e1 = __expf(accS[nt][1]);
                float e2 = __expf(accS[nt][2]);
                float e3 = __expf(accS[nt][3]);
                rs0 += e0 + e1; rs1 += e2 + e3;
                __nv_bfloat16 h0 = __float2bfloat16(e0), h1 = __float2bfloat16(e1);
                __nv_bfloat16 h2 = __float2bfloat16(e2), h3 = __float2bfloat16(e3);
                pa[ks][2 * h]     = (u32)__bfloat16_as_ushort(h0)
                                  | ((u32)__bfloat16_as_ushort(h1) << 16);
                pa[ks][2 * h + 1] = (u32)__bfloat16_as_ushort(h2)
                                  | ((u32)__bfloat16_as_ushort(h3) << 16);
                pb[ks][2 * h]     = packbf2(e0 - __bfloat162float(h0),
                                            e1 - __bfloat162float(h1));
                pb[ks][2 * h + 1] = packbf2(e2 - __bfloat162float(h2),
                                            e3 - __bfloat162float(h3));
            }
        }

        // ---- out += p . v^T  (M=16, N=128 c, K=64 j) ----
#pragma unroll
        for (int ks = 0; ks < 4; ks++) {
#pragma unroll
            for (int np = 0; np < 8; np++) {
                u32 wh[4], wl[4];
                ldm4(wh, bV + np * (16 * RSV) + ks * 32);
                ldm4(wl, bV + np * (16 * RSV) + ks * 32 + TV);
                mma_bf16(accO[2 * np],     pa[ks], wh);
                mma_bf16(accO[2 * np],     pb[ks], wh);
                mma_bf16(accO[2 * np],     pa[ks], wl);
                mma_bf16(accO[2 * np + 1], pa[ks], wh + 2);
                mma_bf16(accO[2 * np + 1], pb[ks], wh + 2);
                mma_bf16(accO[2 * np + 1], pa[ks], wl + 2);
            }
        }
        CPWAIT(0);          // k(jt+1) arrived
        __syncthreads();    // v buffer free
        if (jt + 1 < NJS) {
            cp_v(sb + O_VH, vh + (size_t)(jt + 1) * 128, tid);
            cp_v(sb + O_VL, vl + (size_t)(jt + 1) * 128, tid);
            CPCOMMIT();
        }
    }

    // ---- rowsum reduce (quad shuffle) + transpose accO into q region ----
    float* rssm = (float*)(sm + O_RS);
    rs0 += __shfl_xor_sync(0xffffffffu, rs0, 1);
    rs0 += __shfl_xor_sync(0xffffffffu, rs0, 2);
    rs1 += __shfl_xor_sync(0xffffffffu, rs1, 1);
    rs1 += __shfl_xor_sync(0xffffffffu, rs1, 2);
    if ((lane & 3) == 0) {
        rssm[warp * 16 + (lane >> 2)]     = rs0;
        rssm[warp * 16 + 8 + (lane >> 2)] = rs1;
    }

    float* trans = (float*)sm;   // 128 c x 68 stride floats = 34816 B (q region)
    {
        const int r = lane >> 2, c0 = 2 * (lane & 3);
        const int iA = warp * 16 + r, iB = iA + 8;
#pragma unroll
        for (int nt = 0; nt < 16; nt++) {
            const int c = nt * 8 + c0;
            trans[c * 68 + iA]       = accO[nt][0];
            trans[(c + 1) * 68 + iA] = accO[nt][1];
            trans[c * 68 + iB]       = accO[nt][2];
            trans[(c + 1) * 68 + iB] = accO[nt][3];
        }
    }
    __syncthreads();

    // ---- coalesced epilogue: /rowsum *gamma + x*se (half-warp per c-row) ----
    const float gam = gamma[0];
    const int ic = (lane & 15) * 4;
    float4 rsv = *(float4*)&rssm[ic];
    const float4 ri = make_float4(1.f / rsv.x, 1.f / rsv.y, 1.f / rsv.z, 1.f / rsv.w);
#pragma unroll
    for (int rp = 0; rp < 16; rp++) {
        const int c = warp * 32 + 2 * rp + (lane >> 4);
        const float sec = g_se[b * CH + c];
        const size_t base = (size_t)(b * CH + c) * NPIX + i0 + ic;
        float4 tv = *(float4*)&trans[c * 68 + ic];
        float4 xv = *(const float4*)&x[base];
        float4 o;
        o.x = gam * (tv.x * ri.x) + xv.x * sec;
        o.y = gam * (tv.y * ri.y) + xv.y * sec;
        o.z = gam * (tv.z * ri.z) + xv.z * sec;
        o.w = gam * (tv.w * ri.w) + xv.w * sec;
        *(float4*)&outp[base] = o;
    }
}

// =============================================================================
extern "C" void kernel_launch(void* const* d_in, const int* in_sizes, int n_in,
                              void* d_out, int out_size)
{
    const float* x     = (const float*)d_in[0];
    const float* Wq    = (const float*)d_in[1];
    const float* bq    = (const float*)d_in[2];
    const float* Wk    = (const float*)d_in[3];
    const float* bk    = (const float*)d_in[4];
    const float* Wv    = (const float*)d_in[5];
    const float* bv    = (const float*)d_in[6];
    const float* w1    = (const float*)d_in[7];
    const float* w2    = (const float*)d_in[8];
    const float* gamma = (const float*)d_in[9];
    float* out = (float*)d_out;

    cudaFuncSetAttribute(fused_attn, cudaFuncAttributeMaxDynamicSharedMemorySize,
                         SMEM_F);

    qkv_kernel<<<dim3(NPIX / 64, BATCH, 3), 256>>>(x, Wq, bq, Wk, bk, Wv, bv);
    mean_kernel<<<BATCH * CH, 256>>>(x);
    se_kernel<<<1, 128>>>(w1, w2);
    fused_attn<<<dim3(NIT, BATCH), 128, SMEM_F>>>(x, gamma, out);
}